// round 4
// baseline (speedup 1.0000x reference)
#include <cuda_runtime.h>
#include <cuda_bf16.h>
#include <cstdint>
#include <math.h>

// ---------------- problem constants ----------------
#define D_MODEL   1024
#define D_INNER   2048
#define D_STATE   64
#define HEADDIM   128
#define NHEADS    16
#define D_CONV    4
#define CONV_DIM  2176            // D_INNER + 2*D_STATE
#define D_IN_PROJ 4240            // 2*D_INNER + 2*D_STATE + NHEADS
#define BATCH     2
#define SEQLEN    4096
#define NROWS     (BATCH*SEQLEN)  // 8192
#define RMS_EPS   1e-5f

// chunked scan
#define LCHUNK    128
#define NCHUNK    (SEQLEN/LCHUNK)   // 32

// ---------------- scratch (static device globals, no runtime alloc) -------
__device__ float g_zx [(size_t)NROWS * D_IN_PROJ];
__device__ float g_xbc[(size_t)NROWS * CONV_DIM];
__device__ float g_dec[(size_t)NROWS * NHEADS];
__device__ float g_y  [(size_t)NROWS * D_INNER];
__device__ float g_yg [(size_t)NROWS * D_INNER];
// per-chunk states: [b][h][c][p][n] ; after combine holds S_entry
__device__ float g_st [(size_t)BATCH * NHEADS * NCHUNK * HEADDIM * D_STATE];
// within-chunk cumulative decay: [b][h][c][l]
__device__ float g_cum[(size_t)BATCH * NHEADS * NCHUNK * LCHUNK];

// ================= helpers =================
__device__ __forceinline__ uint32_t smem_to_u32(const void* p) {
    uint32_t a;
    asm("{ .reg .u64 t; cvta.to.shared.u64 t, %1; cvt.u32.u64 %0, t; }"
        : "=r"(a) : "l"(p));
    return a;
}
__device__ __forceinline__ void split_tf32(float v, uint32_t& hi, uint32_t& lo) {
    float h, l;
    asm("cvt.rna.tf32.f32 %0, %1;" : "=f"(h) : "f"(v));
    float r = v - h;
    asm("cvt.rna.tf32.f32 %0, %1;" : "=f"(l) : "f"(r));
    hi = __float_as_uint(h);
    lo = __float_as_uint(l);
}
__device__ __forceinline__ void mma_16n8k8(float* d, const uint32_t* a,
                                           const uint32_t* b) {
    asm volatile(
        "mma.sync.aligned.m16n8k8.row.col.f32.tf32.tf32.f32 "
        "{%0,%1,%2,%3},{%4,%5,%6,%7},{%8,%9},{%0,%1,%2,%3};"
        : "+f"(d[0]), "+f"(d[1]), "+f"(d[2]), "+f"(d[3])
        : "r"(a[0]), "r"(a[1]), "r"(a[2]), "r"(a[3]), "r"(b[0]), "r"(b[1]));
}

// ================= GEMM (mma.sync tf32 3x) ================================
// C[m,n] = sum_k A[m,k]*B[n,k]; A:[M,K], B:[N,K] row-major fp32.
#define GB_M 128
#define GB_N 128
#define GB_K 32
#define GB_SMEM_BYTES (2*128*36*4*2)   // 73728

__global__ __launch_bounds__(256, 2) void gemm_tf32x3(
    const float* __restrict__ A, const float* __restrict__ B,
    float* __restrict__ C, int M, int N, int K)
{
    extern __shared__ char smem[];
    const int tid = threadIdx.x;
    const int bm  = blockIdx.y * GB_M;
    const int bn  = blockIdx.x * GB_N;
    const int nch = K / GB_K;

    float* As = (float*)smem;
    float* Bs = As + 2 * 128 * 36;
    const uint32_t sA = smem_to_u32(As);
    const uint32_t sB = smem_to_u32(Bs);

    const int warp = tid >> 5;
    const int lane = tid & 31;
    const int wm = warp >> 2;     // 0..1
    const int wn = warp & 3;      // 0..3

    float acc[4][4][4];
    #pragma unroll
    for (int mt = 0; mt < 4; mt++)
        #pragma unroll
        for (int nt = 0; nt < 4; nt++)
            #pragma unroll
            for (int q = 0; q < 4; q++) acc[mt][nt][q] = 0.f;

    auto load_stage = [&](int buf, int kt) {
        #pragma unroll
        for (int i = 0; i < 4; i++) {
            int idx = tid + i * 256;     // 0..1023
            int row = idx >> 3, q = idx & 7;
            uint32_t sa = sA + (uint32_t)(buf * 128 * 36 + row * 36 + q * 4) * 4;
            const float* g = A + (size_t)(bm + row) * K + kt + q * 4;
            asm volatile("cp.async.cg.shared.global [%0], [%1], 16;"
                         :: "r"(sa), "l"(g));
        }
        #pragma unroll
        for (int i = 0; i < 4; i++) {
            int idx = tid + i * 256;
            int row = idx >> 3, q = idx & 7;
            int gn = bn + row; if (gn >= N) gn = N - 1;
            uint32_t sbb = sB + (uint32_t)(buf * 128 * 36 + row * 36 + q * 4) * 4;
            const float* g = B + (size_t)gn * K + kt + q * 4;
            asm volatile("cp.async.cg.shared.global [%0], [%1], 16;"
                         :: "r"(sbb), "l"(g));
        }
        asm volatile("cp.async.commit_group;");
    };

    load_stage(0, 0);
    if (nch > 1) load_stage(1, GB_K);

    const int lr = lane >> 2;     // 0..7
    const int lc = lane & 3;      // 0..3

    for (int c = 0; c < nch; c++) {
        if (c + 1 < nch) asm volatile("cp.async.wait_group 1;");
        else             asm volatile("cp.async.wait_group 0;");
        __syncthreads();

        const int abase = (c & 1) * 128 * 36;
        const int bbase = (c & 1) * 128 * 36;

        #pragma unroll
        for (int ks = 0; ks < 4; ks++) {
            uint32_t ahi[4][4], alo[4][4];
            #pragma unroll
            for (int mt = 0; mt < 4; mt++) {
                int r0 = wm * 64 + mt * 16 + lr;
                int k0 = ks * 8 + lc;
                split_tf32(As[abase + r0 * 36 + k0],           ahi[mt][0], alo[mt][0]);
                split_tf32(As[abase + (r0 + 8) * 36 + k0],     ahi[mt][1], alo[mt][1]);
                split_tf32(As[abase + r0 * 36 + k0 + 4],       ahi[mt][2], alo[mt][2]);
                split_tf32(As[abase + (r0 + 8) * 36 + k0 + 4], ahi[mt][3], alo[mt][3]);
            }
            uint32_t bhi[4][2], blo[4][2];
            #pragma unroll
            for (int nt = 0; nt < 4; nt++) {
                int n0 = wn * 32 + nt * 8 + lr;
                int k0 = ks * 8 + lc;
                split_tf32(Bs[bbase + n0 * 36 + k0],     bhi[nt][0], blo[nt][0]);
                split_tf32(Bs[bbase + n0 * 36 + k0 + 4], bhi[nt][1], blo[nt][1]);
            }
            #pragma unroll
            for (int mt = 0; mt < 4; mt++)
                #pragma unroll
                for (int nt = 0; nt < 4; nt++) {
                    mma_16n8k8(acc[mt][nt], ahi[mt], bhi[nt]);
                    mma_16n8k8(acc[mt][nt], ahi[mt], blo[nt]);
                    mma_16n8k8(acc[mt][nt], alo[mt], bhi[nt]);
                }
        }
        __syncthreads();
        if (c + 2 < nch) load_stage(c & 1, (c + 2) * GB_K);
    }

    // epilogue
    #pragma unroll
    for (int mt = 0; mt < 4; mt++) {
        int row = bm + wm * 64 + mt * 16 + lr;
        #pragma unroll
        for (int nt = 0; nt < 4; nt++) {
            int col = bn + wn * 32 + nt * 8 + lc * 2;
            if (col < N) {
                *(float2*)(C + (size_t)row * N + col) =
                    make_float2(acc[mt][nt][0], acc[mt][nt][1]);
                *(float2*)(C + (size_t)(row + 8) * N + col) =
                    make_float2(acc[mt][nt][2], acc[mt][nt][3]);
            }
        }
    }
}

// ---------------- depthwise causal conv (k=4) + bias + SiLU ----------------
__global__ __launch_bounds__(256) void conv_kernel(
    const float* __restrict__ zx, const float* __restrict__ cw,
    const float* __restrict__ cb, float* __restrict__ xbc)
{
    int c = blockIdx.x * 256 + threadIdx.x;
    if (c >= CONV_DIM) return;
    int strip = blockIdx.y;
    int b     = blockIdx.z;
    int l0    = strip * 256;

    float w0 = cw[c*4+0], w1 = cw[c*4+1], w2 = cw[c*4+2], w3 = cw[c*4+3];
    float bias = cb[c];

    size_t colbase = (size_t)D_INNER + c;
    size_t rb = (size_t)b * SEQLEN;

    float xm3 = (l0-3 >= 0) ? zx[(rb + l0-3) * D_IN_PROJ + colbase] : 0.f;
    float xm2 = (l0-2 >= 0) ? zx[(rb + l0-2) * D_IN_PROJ + colbase] : 0.f;
    float xm1 = (l0-1 >= 0) ? zx[(rb + l0-1) * D_IN_PROJ + colbase] : 0.f;

    for (int l = l0; l < l0 + 256; l++) {
        float xv = zx[(rb + l) * D_IN_PROJ + colbase];
        float a = bias;
        a = fmaf(w0, xm3, a);
        a = fmaf(w1, xm2, a);
        a = fmaf(w2, xm1, a);
        a = fmaf(w3, xv,  a);
        float sv = a / (1.f + expf(-a));
        xbc[(rb + l) * CONV_DIM + c] = sv;
        xm3 = xm2; xm2 = xm1; xm1 = xv;
    }
}

// ---------------- dt -> softplus -> decay ----------------------------------
__global__ __launch_bounds__(256) void decay_kernel(
    const float* __restrict__ zx, const float* __restrict__ dt_bias,
    const float* __restrict__ A_log, float* __restrict__ dec)
{
    int idx = blockIdx.x * 256 + threadIdx.x;
    if (idx >= NROWS * NHEADS) return;
    int r = idx >> 4;
    int h = idx & 15;
    float raw = zx[(size_t)r * D_IN_PROJ + (D_IN_PROJ - NHEADS) + h] + dt_bias[h];
    float sp  = (raw > 20.f) ? raw : log1pf(expf(raw));
    float A   = -expf(A_log[h]);
    dec[idx]  = expf(sp * A);
}

// ---------------- chunked scan: stage 1 (local scan per chunk) -------------
// grid (pb=4, h=16, b*NCHUNK + c), block 128.
__global__ __launch_bounds__(128) void scan_local_kernel(
    const float* __restrict__ xbc, const float* __restrict__ dec,
    const float* __restrict__ Dvec, float* __restrict__ yout,
    float* __restrict__ states, float* __restrict__ cumout)
{
    const int pb = blockIdx.x;
    const int h  = blockIdx.y;
    const int c  = blockIdx.z % NCHUNK;
    const int b  = blockIdx.z / NCHUNK;
    const int tid = threadIdx.x;
    const int pl = tid >> 2;
    const int nq = tid & 3;

    __shared__ float sB[2][64], sC[2][64], sx[2][32];
    __shared__ float sdec[2];

    float s[16];
    #pragma unroll
    for (int j = 0; j < 16; j++) s[j] = 0.f;
    const float Dh = Dvec[h];

    const size_t base = (size_t)b * SEQLEN + (size_t)c * LCHUNK;
    const int xcol = h * HEADDIM + pb * 32;
    const size_t cumbase = (size_t)(((b * NHEADS + h) * NCHUNK) + c) * LCHUNK;

    float r0 = 0.f, r1 = 0.f, rdec = 0.f;

    auto ld_regs = [&](int l) {
        size_t row = (base + l) * CONV_DIM;
        if (tid < 64)       r0 = xbc[row + D_INNER + tid];
        else                r0 = xbc[row + D_INNER + 64 + (tid - 64)];
        if (tid < 32)       r1 = xbc[row + xcol + tid];
        if (tid == 127)     rdec = dec[(base + l) * NHEADS + h];
    };
    auto sts = [&](int buf) {
        if (tid < 64)   sB[buf][tid] = r0;
        else            sC[buf][tid - 64] = r0;
        if (tid < 32)   sx[buf][tid] = r1;
        if (tid == 127) sdec[buf] = rdec;
    };

    ld_regs(0); sts(0);
    ld_regs(1);
    __syncthreads();

    float cum = 1.f;

    for (int l = 0; l < LCHUNK; l++) {
        int cur = l & 1;
        if (l + 1 < LCHUNK) sts(cur ^ 1);
        if (l + 2 < LCHUNK) ld_regs(l + 2);

        float dcy = sdec[cur];
        float xv  = sx[cur][pl];
        const float4* B4 = (const float4*)&sB[cur][nq * 16];
        const float4* C4 = (const float4*)&sC[cur][nq * 16];

        float y0 = 0.f, y1 = 0.f, y2 = 0.f, y3 = 0.f;
        #pragma unroll
        for (int q = 0; q < 4; q++) {
            float4 bq = B4[q];
            float4 cq = C4[q];
            s[q*4+0] = fmaf(s[q*4+0], dcy, bq.x * xv);  y0 = fmaf(s[q*4+0], cq.x, y0);
            s[q*4+1] = fmaf(s[q*4+1], dcy, bq.y * xv);  y1 = fmaf(s[q*4+1], cq.y, y1);
            s[q*4+2] = fmaf(s[q*4+2], dcy, bq.z * xv);  y2 = fmaf(s[q*4+2], cq.z, y2);
            s[q*4+3] = fmaf(s[q*4+3], dcy, bq.w * xv);  y3 = fmaf(s[q*4+3], cq.w, y3);
        }
        float y = (y0 + y1) + (y2 + y3);
        y += __shfl_xor_sync(0xffffffffu, y, 1);
        y += __shfl_xor_sync(0xffffffffu, y, 2);

        cum *= dcy;
        if (pb == 0 && tid == 0) cumout[cumbase + l] = cum;
        if (nq == 0)
            yout[(base + l) * D_INNER + xcol + pl] = fmaf(Dh, xv, y);
        __syncthreads();
    }

    // write final local state: [b][h][c][p][n]
    const int p = pb * 32 + pl;
    float* st = states +
        ((size_t)(((b * NHEADS + h) * NCHUNK) + c) * HEADDIM + p) * D_STATE + nq * 16;
    #pragma unroll
    for (int q = 0; q < 4; q++)
        *(float4*)(st + q * 4) = make_float4(s[q*4+0], s[q*4+1], s[q*4+2], s[q*4+3]);
}

// ---------------- chunked scan: stage 2 (combine across chunks) ------------
// grid (h=16, b=2), 256 threads; in-place: g_st becomes S_entry per chunk.
__global__ __launch_bounds__(256) void scan_combine_kernel(
    float* __restrict__ states, const float* __restrict__ cum)
{
    const int h = blockIdx.x;
    const int b = blockIdx.y;
    const int tid = threadIdx.x;

    __shared__ float dprod[NCHUNK];
    if (tid < NCHUNK)
        dprod[tid] = cum[(size_t)(((b * NHEADS + h) * NCHUNK) + tid) * LCHUNK + LCHUNK - 1];
    __syncthreads();

    const size_t chunk_stride = (size_t)HEADDIM * D_STATE;        // 8192 floats
    float* base = states + (size_t)((b * NHEADS + h) * NCHUNK) * chunk_stride;

    // 8192 floats = 2048 float4; 256 threads x 8 float4
    float4 e[8];
    #pragma unroll
    for (int k = 0; k < 8; k++) e[k] = make_float4(0.f, 0.f, 0.f, 0.f);

    for (int c = 0; c < NCHUNK; c++) {
        float d = dprod[c];
        float4* p = (float4*)(base + c * chunk_stride);
        #pragma unroll
        for (int k = 0; k < 8; k++) {
            int idx = tid + k * 256;
            float4 sl = p[idx];
            p[idx] = e[k];
            e[k].x = fmaf(e[k].x, d, sl.x);
            e[k].y = fmaf(e[k].y, d, sl.y);
            e[k].z = fmaf(e[k].z, d, sl.z);
            e[k].w = fmaf(e[k].w, d, sl.w);
        }
    }
}

// ---------------- chunked scan: stage 3 (cross-chunk correction) -----------
// grid (c=32, h=16, b=2), 128 threads (thread = p).
__global__ __launch_bounds__(128) void scan_fix_kernel(
    const float* __restrict__ states, const float* __restrict__ cum,
    const float* __restrict__ xbc, float* __restrict__ yout)
{
    const int c = blockIdx.x;
    if (c == 0) return;                    // entry state is zero
    const int h = blockIdx.y;
    const int b = blockIdx.z;
    const int p = threadIdx.x;

    // load this thread's entry row S_entry[p][0..63] into registers
    float4 ent[16];
    const float* st = states +
        ((size_t)(((b * NHEADS + h) * NCHUNK) + c) * HEADDIM + p) * D_STATE;
    #pragma unroll
    for (int q = 0; q < 16; q++) ent[q] = *(const float4*)(st + q * 4);

    const size_t base = (size_t)b * SEQLEN + (size_t)c * LCHUNK;
    const size_t cumbase = (size_t)(((b * NHEADS + h) * NCHUNK) + c) * LCHUNK;
    const int ycol = h * HEADDIM + p;

    for (int l = 0; l < LCHUNK; l++) {
        const float* Cg = xbc + (base + l) * CONV_DIM + D_INNER + 64;
        float a0 = 0.f, a1 = 0.f, a2 = 0.f, a3 = 0.f;
        #pragma unroll
        for (int q = 0; q < 16; q += 4) {
            float4 c0 = __ldg((const float4*)(Cg + (q + 0) * 4));
            float4 c1 = __ldg((const float4*)(Cg + (q + 1) * 4));
            float4 c2 = __ldg((const float4*)(Cg + (q + 2) * 4));
            float4 c3 = __ldg((const float4*)(Cg + (q + 3) * 4));
            a0 = fmaf(ent[q+0].x, c0.x, a0); a0 = fmaf(ent[q+0].y, c0.y, a0);
            a0 = fmaf(ent[q+0].z, c0.z, a0); a0 = fmaf(ent[q+0].w, c0.w, a0);
            a1 = fmaf(ent[q+1].x, c1.x, a1); a1 = fmaf(ent[q+1].y, c1.y, a1);
            a1 = fmaf(ent[q+1].z, c1.z, a1); a1 = fmaf(ent[q+1].w, c1.w, a1);
            a2 = fmaf(ent[q+2].x, c2.x, a2); a2 = fmaf(ent[q+2].y, c2.y, a2);
            a2 = fmaf(ent[q+2].z, c2.z, a2); a2 = fmaf(ent[q+2].w, c2.w, a2);
            a3 = fmaf(ent[q+3].x, c3.x, a3); a3 = fmaf(ent[q+3].y, c3.y, a3);
            a3 = fmaf(ent[q+3].z, c3.z, a3); a3 = fmaf(ent[q+3].w, c3.w, a3);
        }
        float dot = (a0 + a1) + (a2 + a3);
        float cm = __ldg(cum + cumbase + l);
        float* yp = yout + (base + l) * D_INNER + ycol;
        *yp = fmaf(cm, dot, *yp);
    }
}

// ---------------- RMSNorm + sigmoid(z) gate --------------------------------
__global__ __launch_bounds__(256) void rms_gate_kernel(
    const float* __restrict__ y, const float* __restrict__ zx,
    const float* __restrict__ rmsw, float* __restrict__ yg)
{
    int r = blockIdx.x;
    const float*  yr = y  + (size_t)r * D_INNER;
    const float*  zr = zx + (size_t)r * D_IN_PROJ;
    const float4* y4 = (const float4*)yr;

    int tid = threadIdx.x;
    float ss = 0.f;
    #pragma unroll
    for (int i = 0; i < 2; i++) {
        float4 v = y4[tid + i * 256];
        ss += v.x*v.x + v.y*v.y + v.z*v.z + v.w*v.w;
    }
    #pragma unroll
    for (int o = 16; o > 0; o >>= 1) ss += __shfl_xor_sync(0xffffffffu, ss, o);
    __shared__ float red[8];
    if ((tid & 31) == 0) red[tid >> 5] = ss;
    __syncthreads();
    if (tid == 0) {
        float t = 0.f;
        #pragma unroll
        for (int i = 0; i < 8; i++) t += red[i];
        red[0] = rsqrtf(t * (1.f / D_INNER) + RMS_EPS);
    }
    __syncthreads();
    float rs = red[0];

    const float4* z4 = (const float4*)zr;
    const float4* w4 = (const float4*)rmsw;
    float4*       g4 = (float4*)(yg + (size_t)r * D_INNER);
    #pragma unroll
    for (int i = 0; i < 2; i++) {
        int c = tid + i * 256;
        float4 v = y4[c];
        float4 z = z4[c];
        float4 w = w4[c];
        float4 o;
        o.x = v.x * rs * w.x * (1.f / (1.f + expf(-z.x)));
        o.y = v.y * rs * w.y * (1.f / (1.f + expf(-z.y)));
        o.z = v.z * rs * w.z * (1.f / (1.f + expf(-z.z)));
        o.w = v.w * rs * w.w * (1.f / (1.f + expf(-z.w)));
        g4[c] = o;
    }
}

// ---------------- launcher -------------------------------------------------
extern "C" void kernel_launch(void* const* d_in, const int* in_sizes, int n_in,
                              void* d_out, int out_size)
{
    const float* u        = (const float*)d_in[0];
    const float* in_proj  = (const float*)d_in[1];
    const float* conv_w   = (const float*)d_in[2];
    const float* conv_b   = (const float*)d_in[3];
    const float* dt_bias  = (const float*)d_in[4];
    const float* A_log    = (const float*)d_in[5];
    const float* Dv       = (const float*)d_in[6];
    const float* rms_w    = (const float*)d_in[7];
    const float* out_w    = (const float*)d_in[8];
    float* out = (float*)d_out;

    float *zx, *xbc, *dec, *y, *yg, *st, *cum;
    cudaGetSymbolAddress((void**)&zx,  g_zx);
    cudaGetSymbolAddress((void**)&xbc, g_xbc);
    cudaGetSymbolAddress((void**)&dec, g_dec);
    cudaGetSymbolAddress((void**)&y,   g_y);
    cudaGetSymbolAddress((void**)&yg,  g_yg);
    cudaGetSymbolAddress((void**)&st,  g_st);
    cudaGetSymbolAddress((void**)&cum, g_cum);

    cudaFuncSetAttribute(gemm_tf32x3,
        cudaFuncAttributeMaxDynamicSharedMemorySize, GB_SMEM_BYTES);

    // 1) in_proj
    {
        dim3 grid((D_IN_PROJ + GB_N - 1) / GB_N, NROWS / GB_M);
        gemm_tf32x3<<<grid, 256, GB_SMEM_BYTES>>>(u, in_proj, zx,
                                                  NROWS, D_IN_PROJ, D_MODEL);
    }
    // 2) conv + silu
    {
        dim3 grid((CONV_DIM + 255) / 256, SEQLEN / 256, BATCH);
        conv_kernel<<<grid, 256>>>(zx, conv_w, conv_b, xbc);
    }
    // 3) decay precompute
    decay_kernel<<<(NROWS * NHEADS + 255) / 256, 256>>>(zx, dt_bias, A_log, dec);
    // 4) chunked SSM scan
    {
        dim3 grid(HEADDIM / 32, NHEADS, BATCH * NCHUNK);
        scan_local_kernel<<<grid, 128>>>(xbc, dec, Dv, y, st, cum);
    }
    {
        dim3 grid(NHEADS, BATCH);
        scan_combine_kernel<<<grid, 256>>>(st, cum);
    }
    {
        dim3 grid(NCHUNK, NHEADS, BATCH);
        scan_fix_kernel<<<grid, 128>>>(st, cum, xbc, y);
    }
    // 5) rmsnorm + gate
    rms_gate_kernel<<<NROWS, 256>>>(y, zx, rms_w, yg);
    // 6) out_proj
    {
        dim3 grid(D_MODEL / GB_N, NROWS / GB_M);
        gemm_tf32x3<<<grid, 256, GB_SMEM_BYTES>>>(yg, out_w, out,
                                                  NROWS, D_MODEL, D_INNER);
    }
}

// round 5
// speedup vs baseline: 1.6728x; 1.6728x over previous
#include <cuda_runtime.h>
#include <cuda_bf16.h>
#include <cstdint>
#include <math.h>

// ---------------- problem constants ----------------
#define D_MODEL   1024
#define D_INNER   2048
#define D_STATE   64
#define HEADDIM   128
#define NHEADS    16
#define D_CONV    4
#define CONV_DIM  2176
#define D_IN_PROJ 4240
#define BATCH     2
#define SEQLEN    4096
#define NROWS     (BATCH*SEQLEN)  // 8192
#define RMS_EPS   1e-5f

#define LCHUNK    128
#define NCHUNK    (SEQLEN/LCHUNK)   // 32

// ---------------- scratch ----------------
__device__ float g_zx [(size_t)NROWS * D_IN_PROJ];
__device__ float g_xbc[(size_t)NROWS * CONV_DIM];
__device__ float g_dec[(size_t)NROWS * NHEADS];
__device__ float g_y  [(size_t)NROWS * D_INNER];
__device__ float g_st [(size_t)BATCH * NHEADS * NCHUNK * HEADDIM * D_STATE];
__device__ float g_cum[(size_t)BATCH * NHEADS * NCHUNK * LCHUNK];
// bf16 split operands
__device__ __nv_bfloat16 g_uhi [(size_t)NROWS * D_MODEL];
__device__ __nv_bfloat16 g_ulo [(size_t)NROWS * D_MODEL];
__device__ __nv_bfloat16 g_w1hi[(size_t)D_IN_PROJ * D_MODEL];
__device__ __nv_bfloat16 g_w1lo[(size_t)D_IN_PROJ * D_MODEL];
__device__ __nv_bfloat16 g_w2hi[(size_t)D_MODEL * D_INNER];
__device__ __nv_bfloat16 g_w2lo[(size_t)D_MODEL * D_INNER];
__device__ __nv_bfloat16 g_yghi[(size_t)NROWS * D_INNER];
__device__ __nv_bfloat16 g_yglo[(size_t)NROWS * D_INNER];

// ================= helpers =================
__device__ __forceinline__ uint32_t smem_to_u32(const void* p) {
    uint32_t a;
    asm("{ .reg .u64 t; cvta.to.shared.u64 t, %1; cvt.u32.u64 %0, t; }"
        : "=r"(a) : "l"(p));
    return a;
}
// pack two floats -> bf16x2 (lower half = first arg)
__device__ __forceinline__ uint32_t pack_bf16(float lo_elem, float hi_elem) {
    uint32_t r;
    asm("cvt.rn.bf16x2.f32 %0, %1, %2;" : "=r"(r) : "f"(hi_elem), "f"(lo_elem));
    return r;
}
__device__ __forceinline__ void mma_bf16(float* d, const uint32_t* a,
                                         const uint32_t* b) {
    asm volatile(
        "mma.sync.aligned.m16n8k16.row.col.f32.bf16.bf16.f32 "
        "{%0,%1,%2,%3},{%4,%5,%6,%7},{%8,%9},{%0,%1,%2,%3};"
        : "+f"(d[0]), "+f"(d[1]), "+f"(d[2]), "+f"(d[3])
        : "r"(a[0]), "r"(a[1]), "r"(a[2]), "r"(a[3]), "r"(b[0]), "r"(b[1]));
}

// ================= split kernel: fp32 -> bf16 hi + bf16 lo =================
__global__ __launch_bounds__(256) void split_kernel(
    const float* __restrict__ in, __nv_bfloat16* __restrict__ hi,
    __nv_bfloat16* __restrict__ lo, int n4)
{
    int i = blockIdx.x * 256 + threadIdx.x;
    if (i >= n4) return;
    float4 v = ((const float4*)in)[i];
    uint32_t h01 = pack_bf16(v.x, v.y);
    uint32_t h23 = pack_bf16(v.z, v.w);
    float h0 = __uint_as_float(h01 << 16);
    float h1 = __uint_as_float(h01 & 0xffff0000u);
    float h2 = __uint_as_float(h23 << 16);
    float h3 = __uint_as_float(h23 & 0xffff0000u);
    uint32_t l01 = pack_bf16(v.x - h0, v.y - h1);
    uint32_t l23 = pack_bf16(v.z - h2, v.w - h3);
    ((uint2*)hi)[i] = make_uint2(h01, h23);
    ((uint2*)lo)[i] = make_uint2(l01, l23);
}

// ================= GEMM (bf16x3, mma.sync m16n8k16) ========================
// C[m,n] = sum_k A[m,k]*B[n,k]; operands pre-split into bf16 hi/lo.
#define GB_M 128
#define GB_N 128
#define GB_K 32
// smem: 2 stages x 4 tiles x 128 rows x 20 b32 (row data 16 b32 + pad 4)
#define GB_STAGE_B32 10240
#define GB_SMEM_BYTES (2 * GB_STAGE_B32 * 4)   // 81920

__global__ __launch_bounds__(256, 2) void gemm_bf16x3(
    const __nv_bfloat16* __restrict__ Ahi, const __nv_bfloat16* __restrict__ Alo,
    const __nv_bfloat16* __restrict__ Bhi, const __nv_bfloat16* __restrict__ Blo,
    float* __restrict__ C, int M, int N, int K)
{
    extern __shared__ char smem[];
    const uint32_t sbase = smem_to_u32(smem);
    const uint32_t* S = (const uint32_t*)smem;
    const int tid = threadIdx.x;
    const int bm  = blockIdx.y * GB_M;
    const int bn  = blockIdx.x * GB_N;
    const int nch = K / GB_K;

    const int warp = tid >> 5;
    const int lane = tid & 31;
    const int wm = warp >> 2;
    const int wn = warp & 3;
    const int lr = lane >> 2;
    const int lc = lane & 3;

    float acc[4][4][4];
    #pragma unroll
    for (int mt = 0; mt < 4; mt++)
        #pragma unroll
        for (int nt = 0; nt < 4; nt++)
            #pragma unroll
            for (int q = 0; q < 4; q++) acc[mt][nt][q] = 0.f;

    auto load_stage = [&](int buf, int kt) {
        #pragma unroll
        for (int i = 0; i < 8; i++) {
            int idx = tid + i * 256;        // 0..2047
            int q = idx & 3;
            int r = (idx >> 2) & 127;
            int t = idx >> 9;               // 0..3 : Ahi,Alo,Bhi,Blo
            uint32_t so = sbase + (uint32_t)(buf * GB_STAGE_B32 + t * 2560 +
                                             r * 20 + q * 4) * 4;
            const __nv_bfloat16* g;
            if (t == 0)      g = Ahi + (size_t)(bm + r) * K;
            else if (t == 1) g = Alo + (size_t)(bm + r) * K;
            else {
                int gn = bn + r; if (gn >= N) gn = N - 1;
                g = (t == 2 ? Bhi : Blo) + (size_t)gn * K;
            }
            g += kt + q * 8;
            asm volatile("cp.async.cg.shared.global [%0], [%1], 16;"
                         :: "r"(so), "l"(g));
        }
        asm volatile("cp.async.commit_group;");
    };

    load_stage(0, 0);
    if (nch > 1) load_stage(1, GB_K);

    for (int c = 0; c < nch; c++) {
        if (c + 1 < nch) asm volatile("cp.async.wait_group 1;");
        else             asm volatile("cp.async.wait_group 0;");
        __syncthreads();

        const int stg = (c & 1) * GB_STAGE_B32;

        #pragma unroll
        for (int ks = 0; ks < 2; ks++) {
            uint32_t bhi[4][2], blo[4][2];
            #pragma unroll
            for (int nt = 0; nt < 4; nt++) {
                int n0 = wn * 32 + nt * 8 + lr;
                int i0 = stg + 5120 + n0 * 20 + ks * 8 + lc;
                bhi[nt][0] = S[i0];
                bhi[nt][1] = S[i0 + 4];
                blo[nt][0] = S[i0 + 2560];
                blo[nt][1] = S[i0 + 2560 + 4];
            }
            #pragma unroll
            for (int mt = 0; mt < 4; mt++) {
                int r0 = wm * 64 + mt * 16 + lr;
                int i0 = stg + r0 * 20 + ks * 8 + lc;
                uint32_t ahi[4], alo[4];
                ahi[0] = S[i0];
                ahi[1] = S[i0 + 160];        // +8 rows
                ahi[2] = S[i0 + 4];
                ahi[3] = S[i0 + 164];
                alo[0] = S[i0 + 2560];
                alo[1] = S[i0 + 2560 + 160];
                alo[2] = S[i0 + 2560 + 4];
                alo[3] = S[i0 + 2560 + 164];
                #pragma unroll
                for (int nt = 0; nt < 4; nt++) {
                    mma_bf16(acc[mt][nt], ahi, bhi[nt]);
                    mma_bf16(acc[mt][nt], ahi, blo[nt]);
                    mma_bf16(acc[mt][nt], alo, bhi[nt]);
                }
            }
        }
        __syncthreads();
        if (c + 2 < nch) load_stage(c & 1, (c + 2) * GB_K);
    }

    #pragma unroll
    for (int mt = 0; mt < 4; mt++) {
        int row = bm + wm * 64 + mt * 16 + lr;
        #pragma unroll
        for (int nt = 0; nt < 4; nt++) {
            int col = bn + wn * 32 + nt * 8 + lc * 2;
            if (col < N) {
                *(float2*)(C + (size_t)row * N + col) =
                    make_float2(acc[mt][nt][0], acc[mt][nt][1]);
                *(float2*)(C + (size_t)(row + 8) * N + col) =
                    make_float2(acc[mt][nt][2], acc[mt][nt][3]);
            }
        }
    }
}

// ---------------- depthwise causal conv (k=4) + bias + SiLU ----------------
__global__ __launch_bounds__(256) void conv_kernel(
    const float* __restrict__ zx, const float* __restrict__ cw,
    const float* __restrict__ cb, float* __restrict__ xbc)
{
    int c = blockIdx.x * 256 + threadIdx.x;
    if (c >= CONV_DIM) return;
    int strip = blockIdx.y;
    int b     = blockIdx.z;
    int l0    = strip * 256;

    float w0 = cw[c*4+0], w1 = cw[c*4+1], w2 = cw[c*4+2], w3 = cw[c*4+3];
    float bias = cb[c];

    size_t colbase = (size_t)D_INNER + c;
    size_t rb = (size_t)b * SEQLEN;

    float xm3 = (l0-3 >= 0) ? zx[(rb + l0-3) * D_IN_PROJ + colbase] : 0.f;
    float xm2 = (l0-2 >= 0) ? zx[(rb + l0-2) * D_IN_PROJ + colbase] : 0.f;
    float xm1 = (l0-1 >= 0) ? zx[(rb + l0-1) * D_IN_PROJ + colbase] : 0.f;

    for (int l = l0; l < l0 + 256; l++) {
        float xv = zx[(rb + l) * D_IN_PROJ + colbase];
        float a = bias;
        a = fmaf(w0, xm3, a);
        a = fmaf(w1, xm2, a);
        a = fmaf(w2, xm1, a);
        a = fmaf(w3, xv,  a);
        float sv = a / (1.f + expf(-a));
        xbc[(rb + l) * CONV_DIM + c] = sv;
        xm3 = xm2; xm2 = xm1; xm1 = xv;
    }
}

// ---------------- dt -> softplus -> decay ----------------------------------
__global__ __launch_bounds__(256) void decay_kernel(
    const float* __restrict__ zx, const float* __restrict__ dt_bias,
    const float* __restrict__ A_log, float* __restrict__ dec)
{
    int idx = blockIdx.x * 256 + threadIdx.x;
    if (idx >= NROWS * NHEADS) return;
    int r = idx >> 4;
    int h = idx & 15;
    float raw = zx[(size_t)r * D_IN_PROJ + (D_IN_PROJ - NHEADS) + h] + dt_bias[h];
    float sp  = (raw > 20.f) ? raw : log1pf(expf(raw));
    float A   = -expf(A_log[h]);
    dec[idx]  = expf(sp * A);
}

// ---------------- chunked scan: stage 1 (local, register-tiled) ------------
// grid (c=NCHUNK, h, b), 128 threads; thread owns 4 p x 16 n.
__global__ __launch_bounds__(128) void scan_local_kernel(
    const float* __restrict__ xbc, const float* __restrict__ dec,
    const float* __restrict__ Dvec, float* __restrict__ yout,
    float* __restrict__ states, float* __restrict__ cumout)
{
    const int c = blockIdx.x;
    const int h = blockIdx.y;
    const int b = blockIdx.z;
    const int tid = threadIdx.x;
    const int pg = tid >> 2;      // 0..31  -> p = pg*4 .. pg*4+3
    const int nq = tid & 3;       // 0..3   -> n = nq*16 .. +15

    __shared__ float sB[2][64], sC[2][64], sx[2][128];
    __shared__ float sdec[2];

    float s[16][4];               // [n within slice][p within group]
    #pragma unroll
    for (int i = 0; i < 16; i++)
        #pragma unroll
        for (int j = 0; j < 4; j++) s[i][j] = 0.f;

    const float Dh = Dvec[h];
    const size_t base = (size_t)b * SEQLEN + (size_t)c * LCHUNK;
    const int xcol = h * HEADDIM;
    const size_t cumbase = (size_t)(((b * NHEADS + h) * NCHUNK) + c) * LCHUNK;

    float r0 = 0.f, r1 = 0.f, rdec = 0.f;
    auto ld_regs = [&](int l) {
        size_t row = (base + l) * CONV_DIM;
        if (tid < 64) r0 = xbc[row + D_INNER + tid];
        else          r0 = xbc[row + D_INNER + 64 + (tid - 64)];
        r1 = xbc[row + xcol + tid];
        if (tid == 127) rdec = dec[(base + l) * NHEADS + h];
    };
    auto sts = [&](int buf) {
        if (tid < 64) sB[buf][tid] = r0;
        else          sC[buf][tid - 64] = r0;
        sx[buf][tid] = r1;
        if (tid == 127) sdec[buf] = rdec;
    };

    ld_regs(0); sts(0);
    ld_regs(1);
    __syncthreads();

    float cum = 1.f;

    for (int l = 0; l < LCHUNK; l++) {
        int cur = l & 1;
        if (l + 1 < LCHUNK) sts(cur ^ 1);
        if (l + 2 < LCHUNK) ld_regs(l + 2);

        const float dcy = sdec[cur];
        const float4 xq = *(const float4*)&sx[cur][pg * 4];
        float y0 = 0.f, y1 = 0.f, y2 = 0.f, y3 = 0.f;

        #pragma unroll
        for (int q = 0; q < 4; q++) {
            const float4 bq = *(const float4*)&sB[cur][nq * 16 + q * 4];
            const float4 cq = *(const float4*)&sC[cur][nq * 16 + q * 4];
            #define UPD(BN, CN, NI) \
                s[NI][0] = fmaf(s[NI][0], dcy, BN * xq.x); y0 = fmaf(s[NI][0], CN, y0); \
                s[NI][1] = fmaf(s[NI][1], dcy, BN * xq.y); y1 = fmaf(s[NI][1], CN, y1); \
                s[NI][2] = fmaf(s[NI][2], dcy, BN * xq.z); y2 = fmaf(s[NI][2], CN, y2); \
                s[NI][3] = fmaf(s[NI][3], dcy, BN * xq.w); y3 = fmaf(s[NI][3], CN, y3);
            UPD(bq.x, cq.x, q*4+0)
            UPD(bq.y, cq.y, q*4+1)
            UPD(bq.z, cq.z, q*4+2)
            UPD(bq.w, cq.w, q*4+3)
            #undef UPD
        }
        // reduce over nq (lanes differing in bits 0..1)
        y0 += __shfl_xor_sync(0xffffffffu, y0, 1);
        y0 += __shfl_xor_sync(0xffffffffu, y0, 2);
        y1 += __shfl_xor_sync(0xffffffffu, y1, 1);
        y1 += __shfl_xor_sync(0xffffffffu, y1, 2);
        y2 += __shfl_xor_sync(0xffffffffu, y2, 1);
        y2 += __shfl_xor_sync(0xffffffffu, y2, 2);
        y3 += __shfl_xor_sync(0xffffffffu, y3, 1);
        y3 += __shfl_xor_sync(0xffffffffu, y3, 2);

        cum *= dcy;
        if (tid == 0) cumout[cumbase + l] = cum;
        if (nq == 0) {
            float4 o = make_float4(fmaf(Dh, xq.x, y0), fmaf(Dh, xq.y, y1),
                                   fmaf(Dh, xq.z, y2), fmaf(Dh, xq.w, y3));
            *(float4*)&yout[(base + l) * D_INNER + xcol + pg * 4] = o;
        }
        __syncthreads();
    }

    // write final local state: [b][h][c][p][n]
    float* st = states +
        ((size_t)(((b * NHEADS + h) * NCHUNK) + c) * HEADDIM + pg * 4) * D_STATE + nq * 16;
    #pragma unroll
    for (int pp = 0; pp < 4; pp++)
        #pragma unroll
        for (int q = 0; q < 4; q++)
            *(float4*)(st + pp * D_STATE + q * 4) =
                make_float4(s[q*4+0][pp], s[q*4+1][pp], s[q*4+2][pp], s[q*4+3][pp]);
}

// ---------------- chunked scan: stage 2 (combine across chunks) ------------
__global__ __launch_bounds__(256) void scan_combine_kernel(
    float* __restrict__ states, const float* __restrict__ cum)
{
    const int h = blockIdx.x;
    const int b = blockIdx.y;
    const int tid = threadIdx.x;

    __shared__ float dprod[NCHUNK];
    if (tid < NCHUNK)
        dprod[tid] = cum[(size_t)(((b * NHEADS + h) * NCHUNK) + tid) * LCHUNK + LCHUNK - 1];
    __syncthreads();

    const size_t chunk_stride = (size_t)HEADDIM * D_STATE;
    float* base = states + (size_t)((b * NHEADS + h) * NCHUNK) * chunk_stride;

    float4 e[8];
    #pragma unroll
    for (int k = 0; k < 8; k++) e[k] = make_float4(0.f, 0.f, 0.f, 0.f);

    for (int c = 0; c < NCHUNK; c++) {
        float d = dprod[c];
        float4* p = (float4*)(base + c * chunk_stride);
        #pragma unroll
        for (int k = 0; k < 8; k++) {
            int idx = tid + k * 256;
            float4 sl = p[idx];
            p[idx] = e[k];
            e[k].x = fmaf(e[k].x, d, sl.x);
            e[k].y = fmaf(e[k].y, d, sl.y);
            e[k].z = fmaf(e[k].z, d, sl.z);
            e[k].w = fmaf(e[k].w, d, sl.w);
        }
    }
}

// ---------------- chunked scan: stage 3 (cross-chunk correction) -----------
__global__ __launch_bounds__(128) void scan_fix_kernel(
    const float* __restrict__ states, const float* __restrict__ cum,
    const float* __restrict__ xbc, float* __restrict__ yout)
{
    const int c = blockIdx.x;
    if (c == 0) return;
    const int h = blockIdx.y;
    const int b = blockIdx.z;
    const int p = threadIdx.x;

    float4 ent[16];
    const float* st = states +
        ((size_t)(((b * NHEADS + h) * NCHUNK) + c) * HEADDIM + p) * D_STATE;
    #pragma unroll
    for (int q = 0; q < 16; q++) ent[q] = *(const float4*)(st + q * 4);

    const size_t base = (size_t)b * SEQLEN + (size_t)c * LCHUNK;
    const size_t cumbase = (size_t)(((b * NHEADS + h) * NCHUNK) + c) * LCHUNK;
    const int ycol = h * HEADDIM + p;

    for (int l = 0; l < LCHUNK; l++) {
        const float* Cg = xbc + (base + l) * CONV_DIM + D_INNER + 64;
        float a0 = 0.f, a1 = 0.f, a2 = 0.f, a3 = 0.f;
        #pragma unroll
        for (int q = 0; q < 16; q += 4) {
            float4 c0 = __ldg((const float4*)(Cg + (q + 0) * 4));
            float4 c1 = __ldg((const float4*)(Cg + (q + 1) * 4));
            float4 c2 = __ldg((const float4*)(Cg + (q + 2) * 4));
            float4 c3 = __ldg((const float4*)(Cg + (q + 3) * 4));
            a0 = fmaf(ent[q+0].x, c0.x, a0); a0 = fmaf(ent[q+0].y, c0.y, a0);
            a0 = fmaf(ent[q+0].z, c0.z, a0); a0 = fmaf(ent[q+0].w, c0.w, a0);
            a1 = fmaf(ent[q+1].x, c1.x, a1); a1 = fmaf(ent[q+1].y, c1.y, a1);
            a1 = fmaf(ent[q+1].z, c1.z, a1); a1 = fmaf(ent[q+1].w, c1.w, a1);
            a2 = fmaf(ent[q+2].x, c2.x, a2); a2 = fmaf(ent[q+2].y, c2.y, a2);
            a2 = fmaf(ent[q+2].z, c2.z, a2); a2 = fmaf(ent[q+2].w, c2.w, a2);
            a3 = fmaf(ent[q+3].x, c3.x, a3); a3 = fmaf(ent[q+3].y, c3.y, a3);
            a3 = fmaf(ent[q+3].z, c3.z, a3); a3 = fmaf(ent[q+3].w, c3.w, a3);
        }
        float dot = (a0 + a1) + (a2 + a3);
        float cm = __ldg(cum + cumbase + l);
        float* yp = yout + (base + l) * D_INNER + ycol;
        *yp = fmaf(cm, dot, *yp);
    }
}

// ---------------- RMSNorm + gate, fused bf16 split output ------------------
__global__ __launch_bounds__(256) void rms_gate_kernel(
    const float* __restrict__ y, const float* __restrict__ zx,
    const float* __restrict__ rmsw,
    __nv_bfloat16* __restrict__ ygh, __nv_bfloat16* __restrict__ ygl)
{
    int r = blockIdx.x;
    const float*  yr = y  + (size_t)r * D_INNER;
    const float*  zr = zx + (size_t)r * D_IN_PROJ;
    const float4* y4 = (const float4*)yr;

    int tid = threadIdx.x;
    float ss = 0.f;
    #pragma unroll
    for (int i = 0; i < 2; i++) {
        float4 v = y4[tid + i * 256];
        ss += v.x*v.x + v.y*v.y + v.z*v.z + v.w*v.w;
    }
    #pragma unroll
    for (int o = 16; o > 0; o >>= 1) ss += __shfl_xor_sync(0xffffffffu, ss, o);
    __shared__ float red[8];
    if ((tid & 31) == 0) red[tid >> 5] = ss;
    __syncthreads();
    if (tid == 0) {
        float t = 0.f;
        #pragma unroll
        for (int i = 0; i < 8; i++) t += red[i];
        red[0] = rsqrtf(t * (1.f / D_INNER) + RMS_EPS);
    }
    __syncthreads();
    float rs = red[0];

    const float4* z4 = (const float4*)zr;
    const float4* w4 = (const float4*)rmsw;
    uint2* gh = (uint2*)(ygh + (size_t)r * D_INNER);
    uint2* gl = (uint2*)(ygl + (size_t)r * D_INNER);
    #pragma unroll
    for (int i = 0; i < 2; i++) {
        int c = tid + i * 256;
        float4 v = y4[c];
        float4 z = z4[c];
        float4 w = w4[c];
        float4 o;
        o.x = v.x * rs * w.x * (1.f / (1.f + expf(-z.x)));
        o.y = v.y * rs * w.y * (1.f / (1.f + expf(-z.y)));
        o.z = v.z * rs * w.z * (1.f / (1.f + expf(-z.z)));
        o.w = v.w * rs * w.w * (1.f / (1.f + expf(-z.w)));
        uint32_t h01 = pack_bf16(o.x, o.y);
        uint32_t h23 = pack_bf16(o.z, o.w);
        float h0 = __uint_as_float(h01 << 16);
        float h1 = __uint_as_float(h01 & 0xffff0000u);
        float h2 = __uint_as_float(h23 << 16);
        float h3 = __uint_as_float(h23 & 0xffff0000u);
        gh[c] = make_uint2(h01, h23);
        gl[c] = make_uint2(pack_bf16(o.x - h0, o.y - h1),
                           pack_bf16(o.z - h2, o.w - h3));
    }
}

// ---------------- launcher -------------------------------------------------
extern "C" void kernel_launch(void* const* d_in, const int* in_sizes, int n_in,
                              void* d_out, int out_size)
{
    const float* u        = (const float*)d_in[0];
    const float* in_proj  = (const float*)d_in[1];
    const float* conv_w   = (const float*)d_in[2];
    const float* conv_b   = (const float*)d_in[3];
    const float* dt_bias  = (const float*)d_in[4];
    const float* A_log    = (const float*)d_in[5];
    const float* Dv       = (const float*)d_in[6];
    const float* rms_w    = (const float*)d_in[7];
    const float* out_w    = (const float*)d_in[8];
    float* out = (float*)d_out;

    float *zx, *xbc, *dec, *y, *st, *cum;
    __nv_bfloat16 *uhi, *ulo, *w1hi, *w1lo, *w2hi, *w2lo, *yghi, *yglo;
    cudaGetSymbolAddress((void**)&zx,  g_zx);
    cudaGetSymbolAddress((void**)&xbc, g_xbc);
    cudaGetSymbolAddress((void**)&dec, g_dec);
    cudaGetSymbolAddress((void**)&y,   g_y);
    cudaGetSymbolAddress((void**)&st,  g_st);
    cudaGetSymbolAddress((void**)&cum, g_cum);
    cudaGetSymbolAddress((void**)&uhi,  g_uhi);
    cudaGetSymbolAddress((void**)&ulo,  g_ulo);
    cudaGetSymbolAddress((void**)&w1hi, g_w1hi);
    cudaGetSymbolAddress((void**)&w1lo, g_w1lo);
    cudaGetSymbolAddress((void**)&w2hi, g_w2hi);
    cudaGetSymbolAddress((void**)&w2lo, g_w2lo);
    cudaGetSymbolAddress((void**)&yghi, g_yghi);
    cudaGetSymbolAddress((void**)&yglo, g_yglo);

    cudaFuncSetAttribute(gemm_bf16x3,
        cudaFuncAttributeMaxDynamicSharedMemorySize, GB_SMEM_BYTES);

    // 0) split fp32 operands into bf16 hi/lo
    {
        int n4u = NROWS * D_MODEL / 4;
        split_kernel<<<(n4u + 255) / 256, 256>>>(u, uhi, ulo, n4u);
        int n4w1 = D_IN_PROJ * D_MODEL / 4;
        split_kernel<<<(n4w1 + 255) / 256, 256>>>(in_proj, w1hi, w1lo, n4w1);
        int n4w2 = D_MODEL * D_INNER / 4;
        split_kernel<<<(n4w2 + 255) / 256, 256>>>(out_w, w2hi, w2lo, n4w2);
    }
    // 1) in_proj GEMM
    {
        dim3 grid((D_IN_PROJ + GB_N - 1) / GB_N, NROWS / GB_M);
        gemm_bf16x3<<<grid, 256, GB_SMEM_BYTES>>>(uhi, ulo, w1hi, w1lo, zx,
                                                  NROWS, D_IN_PROJ, D_MODEL);
    }
    // 2) conv + silu
    {
        dim3 grid((CONV_DIM + 255) / 256, SEQLEN / 256, BATCH);
        conv_kernel<<<grid, 256>>>(zx, conv_w, conv_b, xbc);
    }
    // 3) decay precompute
    decay_kernel<<<(NROWS * NHEADS + 255) / 256, 256>>>(zx, dt_bias, A_log, dec);
    // 4) chunked SSM scan
    {
        dim3 grid(NCHUNK, NHEADS, BATCH);
        scan_local_kernel<<<grid, 128>>>(xbc, dec, Dv, y, st, cum);
    }
    {
        dim3 grid(NHEADS, BATCH);
        scan_combine_kernel<<<grid, 256>>>(st, cum);
    }
    {
        dim3 grid(NCHUNK, NHEADS, BATCH);
        scan_fix_kernel<<<grid, 128>>>(st, cum, xbc, y);
    }
    // 5) rmsnorm + gate (+ bf16 split)
    rms_gate_kernel<<<NROWS, 256>>>(y, zx, rms_w, yghi, yglo);
    // 6) out_proj GEMM
    {
        dim3 grid(D_MODEL / GB_N, NROWS / GB_M);
        gemm_bf16x3<<<grid, 256, GB_SMEM_BYTES>>>(yghi, yglo, w2hi, w2lo, out,
                                                  NROWS, D_MODEL, D_INNER);
    }
}

// round 6
// speedup vs baseline: 1.9225x; 1.1493x over previous
#include <cuda_runtime.h>
#include <cuda_bf16.h>
#include <cstdint>
#include <math.h>

// ---------------- problem constants ----------------
#define D_MODEL   1024
#define D_INNER   2048
#define D_STATE   64
#define HEADDIM   128
#define NHEADS    16
#define D_CONV    4
#define CONV_DIM  2176
#define D_IN_PROJ 4240
#define BATCH     2
#define SEQLEN    4096
#define NROWS     (BATCH*SEQLEN)  // 8192
#define RMS_EPS   1e-5f

#define LCHUNK    128
#define NCHUNK    (SEQLEN/LCHUNK)   // 32

// ---------------- scratch ----------------
__device__ float g_zx [(size_t)NROWS * D_IN_PROJ];
__device__ float g_xbc[(size_t)NROWS * CONV_DIM];
__device__ float g_dec[(size_t)NROWS * NHEADS];
__device__ float g_y  [(size_t)NROWS * D_INNER];
__device__ float g_st [(size_t)BATCH * NHEADS * NCHUNK * HEADDIM * D_STATE];
__device__ float g_cum[(size_t)BATCH * NHEADS * NCHUNK * LCHUNK];
__device__ __nv_bfloat16 g_uhi [(size_t)NROWS * D_MODEL];
__device__ __nv_bfloat16 g_ulo [(size_t)NROWS * D_MODEL];
__device__ __nv_bfloat16 g_w1hi[(size_t)D_IN_PROJ * D_MODEL];
__device__ __nv_bfloat16 g_w1lo[(size_t)D_IN_PROJ * D_MODEL];
__device__ __nv_bfloat16 g_w2hi[(size_t)D_MODEL * D_INNER];
__device__ __nv_bfloat16 g_w2lo[(size_t)D_MODEL * D_INNER];
__device__ __nv_bfloat16 g_yghi[(size_t)NROWS * D_INNER];
__device__ __nv_bfloat16 g_yglo[(size_t)NROWS * D_INNER];

// ================= helpers =================
__device__ __forceinline__ uint32_t smem_to_u32(const void* p) {
    uint32_t a;
    asm("{ .reg .u64 t; cvta.to.shared.u64 t, %1; cvt.u32.u64 %0, t; }"
        : "=r"(a) : "l"(p));
    return a;
}
__device__ __forceinline__ uint32_t pack_bf16(float lo_elem, float hi_elem) {
    uint32_t r;
    asm("cvt.rn.bf16x2.f32 %0, %1, %2;" : "=r"(r) : "f"(hi_elem), "f"(lo_elem));
    return r;
}
__device__ __forceinline__ void mma_bf16(float* d, const uint32_t* a,
                                         const uint32_t* b) {
    asm volatile(
        "mma.sync.aligned.m16n8k16.row.col.f32.bf16.bf16.f32 "
        "{%0,%1,%2,%3},{%4,%5,%6,%7},{%8,%9},{%0,%1,%2,%3};"
        : "+f"(d[0]), "+f"(d[1]), "+f"(d[2]), "+f"(d[3])
        : "r"(a[0]), "r"(a[1]), "r"(a[2]), "r"(a[3]), "r"(b[0]), "r"(b[1]));
}
__device__ __forceinline__ void ldsm_x4(uint32_t& r0, uint32_t& r1,
                                        uint32_t& r2, uint32_t& r3,
                                        uint32_t addr) {
    asm volatile("ldmatrix.sync.aligned.m8n8.x4.shared.b16 {%0,%1,%2,%3}, [%4];"
                 : "=r"(r0), "=r"(r1), "=r"(r2), "=r"(r3) : "r"(addr));
}

// ================= split kernel: fp32 -> bf16 hi + bf16 lo =================
__global__ __launch_bounds__(256) void split_kernel(
    const float* __restrict__ in, __nv_bfloat16* __restrict__ hi,
    __nv_bfloat16* __restrict__ lo, int n4)
{
    int i = blockIdx.x * 256 + threadIdx.x;
    if (i >= n4) return;
    float4 v = ((const float4*)in)[i];
    uint32_t h01 = pack_bf16(v.x, v.y);
    uint32_t h23 = pack_bf16(v.z, v.w);
    float h0 = __uint_as_float(h01 << 16);
    float h1 = __uint_as_float(h01 & 0xffff0000u);
    float h2 = __uint_as_float(h23 << 16);
    float h3 = __uint_as_float(h23 & 0xffff0000u);
    uint32_t l01 = pack_bf16(v.x - h0, v.y - h1);
    uint32_t l23 = pack_bf16(v.z - h2, v.w - h3);
    ((uint2*)hi)[i] = make_uint2(h01, h23);
    ((uint2*)lo)[i] = make_uint2(l01, l23);
}

// ================= GEMM (bf16x3, ldmatrix + 3-stage cp.async) ==============
// C[m,n] = sum_k A[m,k]*B[n,k]; operands pre-split into bf16 hi/lo.
// SMEM stage (32 KB): Ahi[128][32] @0, Alo @8192, Bhi @16384, Blo @24576.
// Row = 64 B = four 16B chunks; chunk swizzle: c ^= (row>>1)&3.
#define GB_M 128
#define GB_N 128
#define GB_K 32
#define GB_STAGE 32768
#define GB_SMEM_BYTES (3 * GB_STAGE)   // 98304

__global__ __launch_bounds__(256, 2) void gemm_bf16x3(
    const __nv_bfloat16* __restrict__ Ahi, const __nv_bfloat16* __restrict__ Alo,
    const __nv_bfloat16* __restrict__ Bhi, const __nv_bfloat16* __restrict__ Blo,
    float* __restrict__ C, int M, int N, int K)
{
    extern __shared__ char smem[];
    const uint32_t sbase = smem_to_u32(smem);
    const int tid = threadIdx.x;
    const int bm  = blockIdx.y * GB_M;
    const int bn  = blockIdx.x * GB_N;
    const int nch = K / GB_K;

    const int warp = tid >> 5;
    const int lane = tid & 31;
    const int wm = warp >> 2;
    const int wn = warp & 3;
    const int lr = lane >> 2;
    const int lc = lane & 3;

    float acc[4][4][4];
    #pragma unroll
    for (int mt = 0; mt < 4; mt++)
        #pragma unroll
        for (int nt = 0; nt < 4; nt++)
            #pragma unroll
            for (int q = 0; q < 4; q++) acc[mt][nt][q] = 0.f;

    // ---- cp.async stage loader: 2048 16B-chunks / 256 threads = 8 per thread
    auto load_stage = [&](int buf, int kt) {
        #pragma unroll
        for (int i = 0; i < 8; i++) {
            int idx = tid + i * 256;        // 0..2047
            int cq = idx & 3;               // 16B chunk within row
            int r  = (idx >> 2) & 127;      // row within tile
            int t  = idx >> 9;              // 0..3 : Ahi,Alo,Bhi,Blo
            uint32_t so = sbase + (uint32_t)buf * GB_STAGE + (uint32_t)t * 8192 +
                          (uint32_t)r * 64 + (uint32_t)((cq ^ ((r >> 1) & 3)) * 16);
            const __nv_bfloat16* g;
            if (t == 0)      g = Ahi + (size_t)(bm + r) * K;
            else if (t == 1) g = Alo + (size_t)(bm + r) * K;
            else {
                int gn = bn + r; if (gn >= N) gn = N - 1;
                g = (t == 2 ? Bhi : Blo) + (size_t)gn * K;
            }
            g += kt + cq * 8;
            asm volatile("cp.async.cg.shared.global [%0], [%1], 16;"
                         :: "r"(so), "l"(g));
        }
        asm volatile("cp.async.commit_group;");
    };

    load_stage(0, 0);
    if (nch > 1) load_stage(1, GB_K);

    // lane-fixed ldmatrix address pieces
    const int rowA = wm * 64 + ((lane >> 3) & 1) * 8 + (lane & 7);
    const int rowB = wn * 32 + ((lane >> 4) & 1) * 8 + (lane & 7);
    const int sel  = ((lane & 7) >> 1) & 3;
    const int cAq  = (lane >> 4) & 1;        // k-chunk parity for A lanes
    const int cBq  = (lane >> 3) & 1;        // k-chunk parity for B lanes

    for (int c = 0; c < nch; c++) {
        if (c == nch - 1) asm volatile("cp.async.wait_group 0;");
        else              asm volatile("cp.async.wait_group 1;");
        __syncthreads();
        if (c + 2 < nch) load_stage((c + 2) % 3, (c + 2) * GB_K);

        const uint32_t stg = sbase + (uint32_t)(c % 3) * GB_STAGE;
        const uint32_t baseAhi = stg + (uint32_t)rowA * 64;
        const uint32_t baseAlo = baseAhi + 8192;
        const uint32_t baseBhi = stg + 16384 + (uint32_t)rowB * 64;
        const uint32_t baseBlo = baseBhi + 8192;

        #pragma unroll
        for (int ks = 0; ks < 2; ks++) {
            const uint32_t cAo = (uint32_t)(((ks * 2 + cAq) ^ sel) * 16);
            const uint32_t cBo = (uint32_t)(((ks * 2 + cBq) ^ sel) * 16);

            uint32_t bh[4][2], bl[4][2];
            #pragma unroll
            for (int ntp = 0; ntp < 2; ntp++) {
                uint32_t r0, r1, r2, r3;
                ldsm_x4(r0, r1, r2, r3, baseBhi + ntp * 1024 + cBo);
                bh[ntp*2][0] = r0; bh[ntp*2][1] = r1;
                bh[ntp*2+1][0] = r2; bh[ntp*2+1][1] = r3;
                ldsm_x4(r0, r1, r2, r3, baseBlo + ntp * 1024 + cBo);
                bl[ntp*2][0] = r0; bl[ntp*2][1] = r1;
                bl[ntp*2+1][0] = r2; bl[ntp*2+1][1] = r3;
            }
            #pragma unroll
            for (int mt = 0; mt < 4; mt++) {
                uint32_t ah[4], al[4];
                ldsm_x4(ah[0], ah[1], ah[2], ah[3], baseAhi + mt * 1024 + cAo);
                ldsm_x4(al[0], al[1], al[2], al[3], baseAlo + mt * 1024 + cAo);
                #pragma unroll
                for (int nt = 0; nt < 4; nt++) {
                    mma_bf16(acc[mt][nt], ah, bh[nt]);
                    mma_bf16(acc[mt][nt], ah, bl[nt]);
                    mma_bf16(acc[mt][nt], al, bh[nt]);
                }
            }
        }
    }

    #pragma unroll
    for (int mt = 0; mt < 4; mt++) {
        int row = bm + wm * 64 + mt * 16 + lr;
        #pragma unroll
        for (int nt = 0; nt < 4; nt++) {
            int col = bn + wn * 32 + nt * 8 + lc * 2;
            if (col < N) {
                *(float2*)(C + (size_t)row * N + col) =
                    make_float2(acc[mt][nt][0], acc[mt][nt][1]);
                *(float2*)(C + (size_t)(row + 8) * N + col) =
                    make_float2(acc[mt][nt][2], acc[mt][nt][3]);
            }
        }
    }
}

// ---------------- depthwise causal conv (k=4) + bias + SiLU ----------------
__global__ __launch_bounds__(256) void conv_kernel(
    const float* __restrict__ zx, const float* __restrict__ cw,
    const float* __restrict__ cb, float* __restrict__ xbc)
{
    int c = blockIdx.x * 256 + threadIdx.x;
    if (c >= CONV_DIM) return;
    int strip = blockIdx.y;
    int b     = blockIdx.z;
    int l0    = strip * 256;

    float w0 = cw[c*4+0], w1 = cw[c*4+1], w2 = cw[c*4+2], w3 = cw[c*4+3];
    float bias = cb[c];

    size_t colbase = (size_t)D_INNER + c;
    size_t rb = (size_t)b * SEQLEN;

    float xm3 = (l0-3 >= 0) ? zx[(rb + l0-3) * D_IN_PROJ + colbase] : 0.f;
    float xm2 = (l0-2 >= 0) ? zx[(rb + l0-2) * D_IN_PROJ + colbase] : 0.f;
    float xm1 = (l0-1 >= 0) ? zx[(rb + l0-1) * D_IN_PROJ + colbase] : 0.f;

    for (int l = l0; l < l0 + 256; l++) {
        float xv = zx[(rb + l) * D_IN_PROJ + colbase];
        float a = bias;
        a = fmaf(w0, xm3, a);
        a = fmaf(w1, xm2, a);
        a = fmaf(w2, xm1, a);
        a = fmaf(w3, xv,  a);
        float sv = a / (1.f + expf(-a));
        xbc[(rb + l) * CONV_DIM + c] = sv;
        xm3 = xm2; xm2 = xm1; xm1 = xv;
    }
}

// ---------------- dt -> softplus -> decay ----------------------------------
__global__ __launch_bounds__(256) void decay_kernel(
    const float* __restrict__ zx, const float* __restrict__ dt_bias,
    const float* __restrict__ A_log, float* __restrict__ dec)
{
    int idx = blockIdx.x * 256 + threadIdx.x;
    if (idx >= NROWS * NHEADS) return;
    int r = idx >> 4;
    int h = idx & 15;
    float raw = zx[(size_t)r * D_IN_PROJ + (D_IN_PROJ - NHEADS) + h] + dt_bias[h];
    float sp  = (raw > 20.f) ? raw : log1pf(expf(raw));
    float A   = -expf(A_log[h]);
    dec[idx]  = expf(sp * A);
}

// ---------------- chunked scan: stage 1 (local, register-tiled) ------------
__global__ __launch_bounds__(128) void scan_local_kernel(
    const float* __restrict__ xbc, const float* __restrict__ dec,
    const float* __restrict__ Dvec, float* __restrict__ yout,
    float* __restrict__ states, float* __restrict__ cumout)
{
    const int c = blockIdx.x;
    const int h = blockIdx.y;
    const int b = blockIdx.z;
    const int tid = threadIdx.x;
    const int pg = tid >> 2;
    const int nq = tid & 3;

    __shared__ float sB[2][64], sC[2][64], sx[2][128];
    __shared__ float sdec[2];

    float s[16][4];
    #pragma unroll
    for (int i = 0; i < 16; i++)
        #pragma unroll
        for (int j = 0; j < 4; j++) s[i][j] = 0.f;

    const float Dh = Dvec[h];
    const size_t base = (size_t)b * SEQLEN + (size_t)c * LCHUNK;
    const int xcol = h * HEADDIM;
    const size_t cumbase = (size_t)(((b * NHEADS + h) * NCHUNK) + c) * LCHUNK;

    float r0 = 0.f, r1 = 0.f, rdec = 0.f;
    auto ld_regs = [&](int l) {
        size_t row = (base + l) * CONV_DIM;
        if (tid < 64) r0 = xbc[row + D_INNER + tid];
        else          r0 = xbc[row + D_INNER + 64 + (tid - 64)];
        r1 = xbc[row + xcol + tid];
        if (tid == 127) rdec = dec[(base + l) * NHEADS + h];
    };
    auto sts = [&](int buf) {
        if (tid < 64) sB[buf][tid] = r0;
        else          sC[buf][tid - 64] = r0;
        sx[buf][tid] = r1;
        if (tid == 127) sdec[buf] = rdec;
    };

    ld_regs(0); sts(0);
    ld_regs(1);
    __syncthreads();

    float cum = 1.f;

    for (int l = 0; l < LCHUNK; l++) {
        int cur = l & 1;
        if (l + 1 < LCHUNK) sts(cur ^ 1);
        if (l + 2 < LCHUNK) ld_regs(l + 2);

        const float dcy = sdec[cur];
        const float4 xq = *(const float4*)&sx[cur][pg * 4];
        float y0 = 0.f, y1 = 0.f, y2 = 0.f, y3 = 0.f;

        #pragma unroll
        for (int q = 0; q < 4; q++) {
            const float4 bq = *(const float4*)&sB[cur][nq * 16 + q * 4];
            const float4 cq = *(const float4*)&sC[cur][nq * 16 + q * 4];
            #define UPD(BN, CN, NI) \
                s[NI][0] = fmaf(s[NI][0], dcy, BN * xq.x); y0 = fmaf(s[NI][0], CN, y0); \
                s[NI][1] = fmaf(s[NI][1], dcy, BN * xq.y); y1 = fmaf(s[NI][1], CN, y1); \
                s[NI][2] = fmaf(s[NI][2], dcy, BN * xq.z); y2 = fmaf(s[NI][2], CN, y2); \
                s[NI][3] = fmaf(s[NI][3], dcy, BN * xq.w); y3 = fmaf(s[NI][3], CN, y3);
            UPD(bq.x, cq.x, q*4+0)
            UPD(bq.y, cq.y, q*4+1)
            UPD(bq.z, cq.z, q*4+2)
            UPD(bq.w, cq.w, q*4+3)
            #undef UPD
        }
        y0 += __shfl_xor_sync(0xffffffffu, y0, 1);
        y0 += __shfl_xor_sync(0xffffffffu, y0, 2);
        y1 += __shfl_xor_sync(0xffffffffu, y1, 1);
        y1 += __shfl_xor_sync(0xffffffffu, y1, 2);
        y2 += __shfl_xor_sync(0xffffffffu, y2, 1);
        y2 += __shfl_xor_sync(0xffffffffu, y2, 2);
        y3 += __shfl_xor_sync(0xffffffffu, y3, 1);
        y3 += __shfl_xor_sync(0xffffffffu, y3, 2);

        cum *= dcy;
        if (tid == 0) cumout[cumbase + l] = cum;
        if (nq == 0) {
            float4 o = make_float4(fmaf(Dh, xq.x, y0), fmaf(Dh, xq.y, y1),
                                   fmaf(Dh, xq.z, y2), fmaf(Dh, xq.w, y3));
            *(float4*)&yout[(base + l) * D_INNER + xcol + pg * 4] = o;
        }
        __syncthreads();
    }

    float* st = states +
        ((size_t)(((b * NHEADS + h) * NCHUNK) + c) * HEADDIM + pg * 4) * D_STATE + nq * 16;
    #pragma unroll
    for (int pp = 0; pp < 4; pp++)
        #pragma unroll
        for (int q = 0; q < 4; q++)
            *(float4*)(st + pp * D_STATE + q * 4) =
                make_float4(s[q*4+0][pp], s[q*4+1][pp], s[q*4+2][pp], s[q*4+3][pp]);
}

// ---------------- chunked scan: stage 2 (combine across chunks) ------------
__global__ __launch_bounds__(256) void scan_combine_kernel(
    float* __restrict__ states, const float* __restrict__ cum)
{
    const int h = blockIdx.x;
    const int b = blockIdx.y;
    const int tid = threadIdx.x;

    __shared__ float dprod[NCHUNK];
    if (tid < NCHUNK)
        dprod[tid] = cum[(size_t)(((b * NHEADS + h) * NCHUNK) + tid) * LCHUNK + LCHUNK - 1];
    __syncthreads();

    const size_t chunk_stride = (size_t)HEADDIM * D_STATE;
    float* base = states + (size_t)((b * NHEADS + h) * NCHUNK) * chunk_stride;

    float4 e[8];
    #pragma unroll
    for (int k = 0; k < 8; k++) e[k] = make_float4(0.f, 0.f, 0.f, 0.f);

    for (int c = 0; c < NCHUNK; c++) {
        float d = dprod[c];
        float4* p = (float4*)(base + c * chunk_stride);
        #pragma unroll
        for (int k = 0; k < 8; k++) {
            int idx = tid + k * 256;
            float4 sl = p[idx];
            p[idx] = e[k];
            e[k].x = fmaf(e[k].x, d, sl.x);
            e[k].y = fmaf(e[k].y, d, sl.y);
            e[k].z = fmaf(e[k].z, d, sl.z);
            e[k].w = fmaf(e[k].w, d, sl.w);
        }
    }
}

// ---------------- chunked scan: stage 3 (cross-chunk correction) -----------
__global__ __launch_bounds__(128) void scan_fix_kernel(
    const float* __restrict__ states, const float* __restrict__ cum,
    const float* __restrict__ xbc, float* __restrict__ yout)
{
    const int c = blockIdx.x;
    if (c == 0) return;
    const int h = blockIdx.y;
    const int b = blockIdx.z;
    const int p = threadIdx.x;

    float4 ent[16];
    const float* st = states +
        ((size_t)(((b * NHEADS + h) * NCHUNK) + c) * HEADDIM + p) * D_STATE;
    #pragma unroll
    for (int q = 0; q < 16; q++) ent[q] = *(const float4*)(st + q * 4);

    const size_t base = (size_t)b * SEQLEN + (size_t)c * LCHUNK;
    const size_t cumbase = (size_t)(((b * NHEADS + h) * NCHUNK) + c) * LCHUNK;
    const int ycol = h * HEADDIM + p;

    for (int l = 0; l < LCHUNK; l++) {
        const float* Cg = xbc + (base + l) * CONV_DIM + D_INNER + 64;
        float a0 = 0.f, a1 = 0.f, a2 = 0.f, a3 = 0.f;
        #pragma unroll
        for (int q = 0; q < 16; q += 4) {
            float4 c0 = __ldg((const float4*)(Cg + (q + 0) * 4));
            float4 c1 = __ldg((const float4*)(Cg + (q + 1) * 4));
            float4 c2 = __ldg((const float4*)(Cg + (q + 2) * 4));
            float4 c3 = __ldg((const float4*)(Cg + (q + 3) * 4));
            a0 = fmaf(ent[q+0].x, c0.x, a0); a0 = fmaf(ent[q+0].y, c0.y, a0);
            a0 = fmaf(ent[q+0].z, c0.z, a0); a0 = fmaf(ent[q+0].w, c0.w, a0);
            a1 = fmaf(ent[q+1].x, c1.x, a1); a1 = fmaf(ent[q+1].y, c1.y, a1);
            a1 = fmaf(ent[q+1].z, c1.z, a1); a1 = fmaf(ent[q+1].w, c1.w, a1);
            a2 = fmaf(ent[q+2].x, c2.x, a2); a2 = fmaf(ent[q+2].y, c2.y, a2);
            a2 = fmaf(ent[q+2].z, c2.z, a2); a2 = fmaf(ent[q+2].w, c2.w, a2);
            a3 = fmaf(ent[q+3].x, c3.x, a3); a3 = fmaf(ent[q+3].y, c3.y, a3);
            a3 = fmaf(ent[q+3].z, c3.z, a3); a3 = fmaf(ent[q+3].w, c3.w, a3);
        }
        float dot = (a0 + a1) + (a2 + a3);
        float cm = __ldg(cum + cumbase + l);
        float* yp = yout + (base + l) * D_INNER + ycol;
        *yp = fmaf(cm, dot, *yp);
    }
}

// ---------------- RMSNorm + gate, fused bf16 split output ------------------
__global__ __launch_bounds__(256) void rms_gate_kernel(
    const float* __restrict__ y, const float* __restrict__ zx,
    const float* __restrict__ rmsw,
    __nv_bfloat16* __restrict__ ygh, __nv_bfloat16* __restrict__ ygl)
{
    int r = blockIdx.x;
    const float*  yr = y  + (size_t)r * D_INNER;
    const float*  zr = zx + (size_t)r * D_IN_PROJ;
    const float4* y4 = (const float4*)yr;

    int tid = threadIdx.x;
    float ss = 0.f;
    #pragma unroll
    for (int i = 0; i < 2; i++) {
        float4 v = y4[tid + i * 256];
        ss += v.x*v.x + v.y*v.y + v.z*v.z + v.w*v.w;
    }
    #pragma unroll
    for (int o = 16; o > 0; o >>= 1) ss += __shfl_xor_sync(0xffffffffu, ss, o);
    __shared__ float red[8];
    if ((tid & 31) == 0) red[tid >> 5] = ss;
    __syncthreads();
    if (tid == 0) {
        float t = 0.f;
        #pragma unroll
        for (int i = 0; i < 8; i++) t += red[i];
        red[0] = rsqrtf(t * (1.f / D_INNER) + RMS_EPS);
    }
    __syncthreads();
    float rs = red[0];

    const float4* z4 = (const float4*)zr;
    const float4* w4 = (const float4*)rmsw;
    uint2* gh = (uint2*)(ygh + (size_t)r * D_INNER);
    uint2* gl = (uint2*)(ygl + (size_t)r * D_INNER);
    #pragma unroll
    for (int i = 0; i < 2; i++) {
        int c = tid + i * 256;
        float4 v = y4[c];
        float4 z = z4[c];
        float4 w = w4[c];
        float4 o;
        o.x = v.x * rs * w.x * (1.f / (1.f + expf(-z.x)));
        o.y = v.y * rs * w.y * (1.f / (1.f + expf(-z.y)));
        o.z = v.z * rs * w.z * (1.f / (1.f + expf(-z.z)));
        o.w = v.w * rs * w.w * (1.f / (1.f + expf(-z.w)));
        uint32_t h01 = pack_bf16(o.x, o.y);
        uint32_t h23 = pack_bf16(o.z, o.w);
        float h0 = __uint_as_float(h01 << 16);
        float h1 = __uint_as_float(h01 & 0xffff0000u);
        float h2 = __uint_as_float(h23 << 16);
        float h3 = __uint_as_float(h23 & 0xffff0000u);
        gh[c] = make_uint2(h01, h23);
        gl[c] = make_uint2(pack_bf16(o.x - h0, o.y - h1),
                           pack_bf16(o.z - h2, o.w - h3));
    }
}

// ---------------- launcher -------------------------------------------------
extern "C" void kernel_launch(void* const* d_in, const int* in_sizes, int n_in,
                              void* d_out, int out_size)
{
    const float* u        = (const float*)d_in[0];
    const float* in_proj  = (const float*)d_in[1];
    const float* conv_w   = (const float*)d_in[2];
    const float* conv_b   = (const float*)d_in[3];
    const float* dt_bias  = (const float*)d_in[4];
    const float* A_log    = (const float*)d_in[5];
    const float* Dv       = (const float*)d_in[6];
    const float* rms_w    = (const float*)d_in[7];
    const float* out_w    = (const float*)d_in[8];
    float* out = (float*)d_out;

    float *zx, *xbc, *dec, *y, *st, *cum;
    __nv_bfloat16 *uhi, *ulo, *w1hi, *w1lo, *w2hi, *w2lo, *yghi, *yglo;
    cudaGetSymbolAddress((void**)&zx,  g_zx);
    cudaGetSymbolAddress((void**)&xbc, g_xbc);
    cudaGetSymbolAddress((void**)&dec, g_dec);
    cudaGetSymbolAddress((void**)&y,   g_y);
    cudaGetSymbolAddress((void**)&st,  g_st);
    cudaGetSymbolAddress((void**)&cum, g_cum);
    cudaGetSymbolAddress((void**)&uhi,  g_uhi);
    cudaGetSymbolAddress((void**)&ulo,  g_ulo);
    cudaGetSymbolAddress((void**)&w1hi, g_w1hi);
    cudaGetSymbolAddress((void**)&w1lo, g_w1lo);
    cudaGetSymbolAddress((void**)&w2hi, g_w2hi);
    cudaGetSymbolAddress((void**)&w2lo, g_w2lo);
    cudaGetSymbolAddress((void**)&yghi, g_yghi);
    cudaGetSymbolAddress((void**)&yglo, g_yglo);

    cudaFuncSetAttribute(gemm_bf16x3,
        cudaFuncAttributeMaxDynamicSharedMemorySize, GB_SMEM_BYTES);

    // 0) split fp32 operands into bf16 hi/lo
    {
        int n4u = NROWS * D_MODEL / 4;
        split_kernel<<<(n4u + 255) / 256, 256>>>(u, uhi, ulo, n4u);
        int n4w1 = D_IN_PROJ * D_MODEL / 4;
        split_kernel<<<(n4w1 + 255) / 256, 256>>>(in_proj, w1hi, w1lo, n4w1);
        int n4w2 = D_MODEL * D_INNER / 4;
        split_kernel<<<(n4w2 + 255) / 256, 256>>>(out_w, w2hi, w2lo, n4w2);
    }
    // 1) in_proj GEMM
    {
        dim3 grid((D_IN_PROJ + GB_N - 1) / GB_N, NROWS / GB_M);
        gemm_bf16x3<<<grid, 256, GB_SMEM_BYTES>>>(uhi, ulo, w1hi, w1lo, zx,
                                                  NROWS, D_IN_PROJ, D_MODEL);
    }
    // 2) conv + silu
    {
        dim3 grid((CONV_DIM + 255) / 256, SEQLEN / 256, BATCH);
        conv_kernel<<<grid, 256>>>(zx, conv_w, conv_b, xbc);
    }
    // 3) decay precompute
    decay_kernel<<<(NROWS * NHEADS + 255) / 256, 256>>>(zx, dt_bias, A_log, dec);
    // 4) chunked SSM scan
    {
        dim3 grid(NCHUNK, NHEADS, BATCH);
        scan_local_kernel<<<grid, 128>>>(xbc, dec, Dv, y, st, cum);
    }
    {
        dim3 grid(NHEADS, BATCH);
        scan_combine_kernel<<<grid, 256>>>(st, cum);
    }
    {
        dim3 grid(NCHUNK, NHEADS, BATCH);
        scan_fix_kernel<<<grid, 128>>>(st, cum, xbc, y);
    }
    // 5) rmsnorm + gate (+ bf16 split)
    rms_gate_kernel<<<NROWS, 256>>>(y, zx, rms_w, yghi, yglo);
    // 6) out_proj GEMM
    {
        dim3 grid(D_MODEL / GB_N, NROWS / GB_M);
        gemm_bf16x3<<<grid, 256, GB_SMEM_BYTES>>>(yghi, yglo, w2hi, w2lo, out,
                                                  NROWS, D_MODEL, D_INNER);
    }
}